// round 1
// baseline (speedup 1.0000x reference)
#include <cuda_runtime.h>
#include <cuda_bf16.h>

// NoiseNet: out[e, :] = tanh( concat(node_feats[recv[e]], node_feats[send[e]]) @ W + b )
// E = 800000, D = 64, K = 128, N = 64.
// Inputs (metadata order): node_feats [50000*64] f32, senders [800000] i32,
// receivers [800000] i32, W [128*64] f32, b [64] f32. Output: [800000*64] f32.

#define BM 64            // edges per block
#define K_DIM 128
#define N_DIM 64
#define AS_STRIDE 132    // 128 + 4 pad (keeps float4 alignment, breaks bank aliasing)
#define THREADS 256

// dynamic smem layout: As[BM * AS_STRIDE] floats, then Ws[K_DIM * N_DIM] floats
#define SMEM_FLOATS (BM * AS_STRIDE + K_DIM * N_DIM)

__global__ __launch_bounds__(THREADS, 2)
void noisenet_edge_kernel(const float* __restrict__ node_feats,
                          const int* __restrict__ senders,
                          const int* __restrict__ receivers,
                          const float* __restrict__ W,
                          const float* __restrict__ b,
                          float* __restrict__ out,
                          int n_edges)
{
    extern __shared__ float smem[];
    float* As = smem;                      // [BM][AS_STRIDE]
    float* Ws = smem + BM * AS_STRIDE;     // [K_DIM][N_DIM]

    const int tid = threadIdx.x;
    const int e0 = blockIdx.x * BM;

    // ---- Stage W: 128x64 floats = 2048 float4, 8 per thread, coalesced ----
    {
        const float4* Wg = reinterpret_cast<const float4*>(W);
        float4* Wsv = reinterpret_cast<float4*>(Ws);
        #pragma unroll
        for (int c = tid; c < (K_DIM * N_DIM) / 4; c += THREADS)
            Wsv[c] = Wg[c];
    }

    // ---- Gather A tile: 64 edges x 128 floats (recv first, then send) ----
    // chunk c: edge = c>>5, k4 = c&31 (float4 index). One warp stages one edge
    // per iteration -> consecutive float4 STS, conflict-free & coalesced LDG.
    {
        #pragma unroll
        for (int c = tid; c < BM * 32; c += THREADS) {
            const int e  = c >> 5;
            const int k4 = c & 31;
            const int edge = e0 + e;
            int node;
            if (k4 < 16) node = receivers[edge];
            else         node = senders[edge];
            const int off = k4 & 15;   // float4 within the node's 64-float row
            float4 v = reinterpret_cast<const float4*>(node_feats)[node * 16 + off];
            *reinterpret_cast<float4*>(&As[e * AS_STRIDE + k4 * 4]) = v;
        }
    }
    __syncthreads();

    // ---- Compute: 4x4 register blocking. tx: N dim (16 groups of 4), ty: M dim ----
    const int tx = tid & 15;
    const int ty = tid >> 4;

    float acc[4][4];
    #pragma unroll
    for (int i = 0; i < 4; i++)
        #pragma unroll
        for (int j = 0; j < 4; j++)
            acc[i][j] = 0.0f;

    const float* As_base = &As[(ty * 4) * AS_STRIDE];
    const float* Ws_base = &Ws[tx * 4];

    #pragma unroll 4
    for (int k = 0; k < K_DIM; k++) {
        const float4 w = *reinterpret_cast<const float4*>(&Ws_base[k * N_DIM]);
        float a0 = As_base[0 * AS_STRIDE + k];
        float a1 = As_base[1 * AS_STRIDE + k];
        float a2 = As_base[2 * AS_STRIDE + k];
        float a3 = As_base[3 * AS_STRIDE + k];
        acc[0][0] += a0 * w.x; acc[0][1] += a0 * w.y; acc[0][2] += a0 * w.z; acc[0][3] += a0 * w.w;
        acc[1][0] += a1 * w.x; acc[1][1] += a1 * w.y; acc[1][2] += a1 * w.z; acc[1][3] += a1 * w.w;
        acc[2][0] += a2 * w.x; acc[2][1] += a2 * w.y; acc[2][2] += a2 * w.z; acc[2][3] += a2 * w.w;
        acc[3][0] += a3 * w.x; acc[3][1] += a3 * w.y; acc[3][2] += a3 * w.z; acc[3][3] += a3 * w.w;
    }

    // ---- Epilogue: bias + tanh, vector stores ----
    const float4 bj = *reinterpret_cast<const float4*>(&b[tx * 4]);

    #pragma unroll
    for (int i = 0; i < 4; i++) {
        const int edge = e0 + ty * 4 + i;
        if (edge < n_edges) {
            float4 r;
            r.x = tanhf(acc[i][0] + bj.x);
            r.y = tanhf(acc[i][1] + bj.y);
            r.z = tanhf(acc[i][2] + bj.z);
            r.w = tanhf(acc[i][3] + bj.w);
            *reinterpret_cast<float4*>(&out[edge * N_DIM + tx * 4]) = r;
        }
    }
}

extern "C" void kernel_launch(void* const* d_in, const int* in_sizes, int n_in,
                              void* d_out, int out_size)
{
    const float* node_feats = (const float*)d_in[0];
    const int*   senders    = (const int*)d_in[1];
    const int*   receivers  = (const int*)d_in[2];
    const float* W          = (const float*)d_in[3];
    const float* b          = (const float*)d_in[4];
    float*       out        = (float*)d_out;

    const int n_edges = in_sizes[1];   // senders element count
    const int smem_bytes = SMEM_FLOATS * sizeof(float);

    // Dynamic smem > 48KB needs an explicit opt-in (host call, idempotent,
    // executes immediately — not a captured stream op).
    static bool attr_set = false;
    if (!attr_set) {
        cudaFuncSetAttribute(noisenet_edge_kernel,
                             cudaFuncAttributeMaxDynamicSharedMemorySize,
                             smem_bytes);
        attr_set = true;
    }

    const int grid = (n_edges + BM - 1) / BM;
    noisenet_edge_kernel<<<grid, THREADS, smem_bytes>>>(
        node_feats, senders, receivers, W, b, out, n_edges);
}

// round 3
// speedup vs baseline: 1.6379x; 1.6379x over previous
#include <cuda_runtime.h>
#include <cuda_bf16.h>
#include <cstdint>

// NoiseNet: out[e,:] = tanh( concat(nf[recv[e]], nf[send[e]]) @ W + b )
// E=800000, D=64 -> K=128, N=64.
// Tensor-core path via warp-level mma.sync (m16n8k8, tf32) — compiles for
// plain sm_103 target (tcgen05 PTX is rejected by this harness's ptxas pass).

#define K_DIM 128
#define N_DIM 64
#define TILE_M 128
#define THREADS 256
#define AS_STRIDE 132   // floats; banks (4g + c) unique per warp for frag loads
#define BS_STRIDE 72    // floats; banks (8k + n) unique per warp for frag loads

#define SMEM_FLOATS (TILE_M * AS_STRIDE + K_DIM * BS_STRIDE)
#define SMEM_BYTES  (SMEM_FLOATS * 4)

__device__ __forceinline__ uint32_t f2tf32(float x) {
    uint32_t r;
    asm("cvt.rna.tf32.f32 %0, %1;" : "=r"(r) : "f"(x));
    return r;
}

__device__ __forceinline__ void mma_16x8x8_tf32(float c[4], const uint32_t a[4],
                                                const uint32_t b[2]) {
    asm volatile(
        "mma.sync.aligned.m16n8k8.row.col.f32.tf32.tf32.f32 "
        "{%0,%1,%2,%3}, {%4,%5,%6,%7}, {%8,%9}, {%0,%1,%2,%3};"
        : "+f"(c[0]), "+f"(c[1]), "+f"(c[2]), "+f"(c[3])
        : "r"(a[0]), "r"(a[1]), "r"(a[2]), "r"(a[3]), "r"(b[0]), "r"(b[1]));
}

__global__ __launch_bounds__(THREADS, 2)
void noisenet_mma_kernel(const float* __restrict__ node_feats,
                         const int* __restrict__ senders,
                         const int* __restrict__ receivers,
                         const float* __restrict__ W,
                         const float* __restrict__ bias,
                         float* __restrict__ out,
                         int n_edges)
{
    extern __shared__ uint32_t smem[];
    uint32_t* As = smem;                         // [TILE_M][AS_STRIDE] tf32
    uint32_t* Bs = smem + TILE_M * AS_STRIDE;    // [K_DIM][BS_STRIDE] tf32

    const int tid = threadIdx.x;
    const int wid = tid >> 5;
    const int lid = tid & 31;
    const int e0 = blockIdx.x * TILE_M;

    // ---- Stage B = W[128][64] (row.col mma: B indexed [k][n] directly) ----
    {
        const float4* Wg = reinterpret_cast<const float4*>(W);
        #pragma unroll
        for (int c = tid; c < K_DIM * (N_DIM / 4); c += THREADS) {
            const int k  = c >> 4;       // 16 float4 per k-row
            const int n4 = c & 15;
            float4 v = Wg[c];
            uint32_t* dst = &Bs[k * BS_STRIDE + n4 * 4];
            dst[0] = f2tf32(v.x); dst[1] = f2tf32(v.y);
            dst[2] = f2tf32(v.z); dst[3] = f2tf32(v.w);
        }
    }

    // ---- Gather A: 128 edges x (recv 64 | send 64) -> tf32 smem ----
    {
        const float4* nf4 = reinterpret_cast<const float4*>(node_feats);
        #pragma unroll
        for (int c = tid; c < TILE_M * 32; c += THREADS) {
            const int e = c >> 5;        // edge within tile
            const int q = c & 31;        // float4 index along K (0..31)
            const int edge = e0 + e;
            float4 v = make_float4(0.f, 0.f, 0.f, 0.f);
            if (edge < n_edges) {
                const int node = (q < 16) ? receivers[edge] : senders[edge];
                v = nf4[node * 16 + (q & 15)];
            }
            uint32_t* dst = &As[e * AS_STRIDE + q * 4];
            dst[0] = f2tf32(v.x); dst[1] = f2tf32(v.y);
            dst[2] = f2tf32(v.z); dst[3] = f2tf32(v.w);
        }
    }
    __syncthreads();

    // ---- Compute: warp (wm, wn) owns rows [32*wm, +32), cols [32*wn, +32) ----
    const int wm = wid & 3;
    const int wn = wid >> 2;
    const int g  = lid >> 2;     // group id 0..7
    const int cc = lid & 3;      // thread-in-group 0..3

    float acc[2][4][4];
    #pragma unroll
    for (int mt = 0; mt < 2; mt++)
        #pragma unroll
        for (int nt = 0; nt < 4; nt++)
            #pragma unroll
            for (int r = 0; r < 4; r++)
                acc[mt][nt][r] = 0.0f;

    const int arow0 = wm * 32 + g;           // + 16*mt, +8 for a1/a3
    const int bn0   = wn * 32 + g;           // + 8*nt

    #pragma unroll
    for (int s = 0; s < K_DIM / 8; s++) {
        const int k0 = s * 8;

        uint32_t a[2][4];
        #pragma unroll
        for (int mt = 0; mt < 2; mt++) {
            const uint32_t* ap = &As[(arow0 + mt * 16) * AS_STRIDE + k0 + cc];
            a[mt][0] = ap[0];
            a[mt][1] = ap[8 * AS_STRIDE];
            a[mt][2] = ap[4];
            a[mt][3] = ap[8 * AS_STRIDE + 4];
        }

        uint32_t bf[4][2];
        #pragma unroll
        for (int nt = 0; nt < 4; nt++) {
            const uint32_t* bp = &Bs[(k0 + cc) * BS_STRIDE + bn0 + nt * 8];
            bf[nt][0] = bp[0];
            bf[nt][1] = bp[4 * BS_STRIDE];
        }

        #pragma unroll
        for (int mt = 0; mt < 2; mt++)
            #pragma unroll
            for (int nt = 0; nt < 4; nt++)
                mma_16x8x8_tf32(acc[mt][nt], a[mt], bf[nt]);
    }

    // ---- Epilogue: bias + tanh, float2 stores (full 32B sectors per group) ----
    #pragma unroll
    for (int nt = 0; nt < 4; nt++) {
        const int col = wn * 32 + nt * 8 + 2 * cc;
        const float2 bj = *reinterpret_cast<const float2*>(&bias[col]);
        #pragma unroll
        for (int mt = 0; mt < 2; mt++) {
            const int row0 = wm * 32 + mt * 16 + g;
            const int edge0 = e0 + row0;
            if (edge0 < n_edges) {
                float2 r;
                r.x = tanhf(acc[mt][nt][0] + bj.x);
                r.y = tanhf(acc[mt][nt][1] + bj.y);
                *reinterpret_cast<float2*>(&out[(size_t)edge0 * N_DIM + col]) = r;
            }
            const int edge1 = edge0 + 8;
            if (edge1 < n_edges) {
                float2 r;
                r.x = tanhf(acc[mt][nt][2] + bj.x);
                r.y = tanhf(acc[mt][nt][3] + bj.y);
                *reinterpret_cast<float2*>(&out[(size_t)edge1 * N_DIM + col]) = r;
            }
        }
    }
}

extern "C" void kernel_launch(void* const* d_in, const int* in_sizes, int n_in,
                              void* d_out, int out_size)
{
    const float* node_feats = (const float*)d_in[0];
    const int*   senders    = (const int*)d_in[1];
    const int*   receivers  = (const int*)d_in[2];
    const float* W          = (const float*)d_in[3];
    const float* b          = (const float*)d_in[4];
    float*       out        = (float*)d_out;

    const int n_edges = in_sizes[1];

    static bool attr_set = false;
    if (!attr_set) {
        cudaFuncSetAttribute(noisenet_mma_kernel,
                             cudaFuncAttributeMaxDynamicSharedMemorySize, SMEM_BYTES);
        attr_set = true;
    }

    const int grid = (n_edges + TILE_M - 1) / TILE_M;
    noisenet_mma_kernel<<<grid, THREADS, SMEM_BYTES>>>(
        node_feats, senders, receivers, W, b, out, n_edges);
}

// round 4
// speedup vs baseline: 2.0011x; 1.2217x over previous
#include <cuda_runtime.h>
#include <cuda_bf16.h>
#include <cstdint>

// NoiseNet: out[e,:] = tanh( concat(nf[recv[e]], nf[send[e]]) @ W + b )
// E=800000, D=64 -> K=128, N=64.
// Persistent CTAs, cp.async double-buffered gather, warp-level mma.sync tf32.

#define K_DIM 128
#define N_DIM 64
#define TILE_M 128
#define THREADS 256
#define AS_STRIDE 132   // floats; 528B rows -> 16B aligned, conflict-free frags
#define BS_STRIDE 72    // floats; banks (8cc + g) unique per warp

#define A_BUF_FLOATS (TILE_M * AS_STRIDE)     // 16896 floats = 67584 B
#define B_FLOATS     (K_DIM * BS_STRIDE)      // 9216 floats  = 36864 B
#define SMEM_FLOATS  (2 * A_BUF_FLOATS + B_FLOATS + N_DIM)
#define SMEM_BYTES   (SMEM_FLOATS * 4)        // 172288 B -> 1 CTA/SM

__device__ __forceinline__ uint32_t smem_u32(const void* p) {
    uint32_t a;
    asm("{ .reg .u64 t; cvta.to.shared.u64 t, %1; cvt.u32.u64 %0, t; }" : "=r"(a) : "l"(p));
    return a;
}

__device__ __forceinline__ void cp16(uint32_t dst, const void* src) {
    asm volatile("cp.async.cg.shared.global.L2::128B [%0], [%1], 16;"
                 :: "r"(dst), "l"(src));
}
__device__ __forceinline__ void cp_commit() {
    asm volatile("cp.async.commit_group;" ::: "memory");
}
__device__ __forceinline__ void cp_wait1() {
    asm volatile("cp.async.wait_group 1;" ::: "memory");
}
__device__ __forceinline__ void cp_wait0() {
    asm volatile("cp.async.wait_group 0;" ::: "memory");
}

__device__ __forceinline__ uint32_t f2tf32(float x) {
    uint32_t r;
    asm("cvt.rna.tf32.f32 %0, %1;" : "=r"(r) : "f"(x));
    return r;
}

__device__ __forceinline__ void mma_16x8x8_tf32(float c[4], const uint32_t a[4],
                                                const uint32_t b[2]) {
    asm volatile(
        "mma.sync.aligned.m16n8k8.row.col.f32.tf32.tf32.f32 "
        "{%0,%1,%2,%3}, {%4,%5,%6,%7}, {%8,%9}, {%0,%1,%2,%3};"
        : "+f"(c[0]), "+f"(c[1]), "+f"(c[2]), "+f"(c[3])
        : "r"(a[0]), "r"(a[1]), "r"(a[2]), "r"(a[3]), "r"(b[0]), "r"(b[1]));
}

__global__ __launch_bounds__(THREADS, 1)
void noisenet_pipe_kernel(const float* __restrict__ node_feats,
                          const int* __restrict__ senders,
                          const int* __restrict__ receivers,
                          const float* __restrict__ W,
                          const float* __restrict__ bias,
                          float* __restrict__ out,
                          int n_edges, int n_tiles)
{
    extern __shared__ uint32_t smem[];
    uint32_t* A0 = smem;                               // buf 0
    uint32_t* A1 = smem + A_BUF_FLOATS;                // buf 1
    uint32_t* Bs = smem + 2 * A_BUF_FLOATS;            // [K][BS_STRIDE] tf32
    float*    bs = reinterpret_cast<float*>(Bs + B_FLOATS);  // bias [64]

    const int tid = threadIdx.x;
    const int wid = tid >> 5;
    const int lid = tid & 31;

    const uint32_t a0_addr = smem_u32(A0);
    const uint32_t a1_addr = smem_u32(A1);

    // ---- Stage B = W[128][64] with round-to-nearest tf32; stage bias ----
    {
        const float4* Wg = reinterpret_cast<const float4*>(W);
        #pragma unroll
        for (int c = tid; c < K_DIM * (N_DIM / 4); c += THREADS) {
            const int k  = c >> 4;
            const int n4 = c & 15;
            float4 v = Wg[c];
            uint32_t* dst = &Bs[k * BS_STRIDE + n4 * 4];
            dst[0] = f2tf32(v.x); dst[1] = f2tf32(v.y);
            dst[2] = f2tf32(v.z); dst[3] = f2tf32(v.w);
        }
        if (tid < N_DIM) bs[tid] = bias[tid];
    }

    // Per-thread gather geometry: thread handles edges e_base + 8j, fixed q.
    const int e_base = tid >> 5;       // 0..7
    const int q      = tid & 31;       // float4 index along K
    const int qsel   = (q < 16);       // recv half?
    const int qoff   = (q & 15);
    const uint32_t dst_off = (uint32_t)(q * 16);   // byte offset within row
    const float4* nf4 = reinterpret_cast<const float4*>(node_feats);

    // issue one tile's gather into buffer `abuf`
    auto prefetch = [&](int tile, uint32_t abuf) {
        const int e0 = tile * TILE_M;
        #pragma unroll
        for (int j = 0; j < 16; j++) {
            int e = e_base + 8 * j;
            int edge = e0 + e;
            if (edge >= n_edges) edge = n_edges - 1;   // safe clamp (tail)
            const int node = qsel ? receivers[edge] : senders[edge];
            cp16(abuf + (uint32_t)e * (AS_STRIDE * 4) + dst_off,
                 nf4 + (size_t)node * 16 + qoff);
        }
        cp_commit();
    };

    // fragment geometry
    const int wm = wid & 3;
    const int wn = wid >> 2;
    const int g  = lid >> 2;
    const int cc = lid & 3;
    const int arow0 = wm * 32 + g;
    const int bn0   = wn * 32 + g;

    int tile = blockIdx.x;
    if (tile < n_tiles) prefetch(tile, a0_addr);
    __syncthreads();   // B + bias visible (cp.async still in flight)

    int bufsel = 0;
    for (; tile < n_tiles; tile += gridDim.x) {
        const int next = tile + gridDim.x;
        if (next < n_tiles) {
            prefetch(next, bufsel ? a0_addr : a1_addr);
            cp_wait1();            // current tile's group complete
        } else {
            cp_wait0();
        }
        __syncthreads();           // gathered A visible to all warps

        const uint32_t* As = bufsel ? A1 : A0;
        const int e0 = tile * TILE_M;

        float acc[2][4][4];
        #pragma unroll
        for (int mt = 0; mt < 2; mt++)
            #pragma unroll
            for (int nt = 0; nt < 4; nt++)
                #pragma unroll
                for (int r = 0; r < 4; r++)
                    acc[mt][nt][r] = 0.0f;

        #pragma unroll
        for (int s = 0; s < K_DIM / 8; s++) {
            const int k0 = s * 8;

            uint32_t a[2][4];
            #pragma unroll
            for (int mt = 0; mt < 2; mt++) {
                const uint32_t* ap = &As[(arow0 + mt * 16) * AS_STRIDE + k0 + cc];
                a[mt][0] = ap[0];
                a[mt][1] = ap[8 * AS_STRIDE];
                a[mt][2] = ap[4];
                a[mt][3] = ap[8 * AS_STRIDE + 4];
            }

            uint32_t bf[4][2];
            #pragma unroll
            for (int nt = 0; nt < 4; nt++) {
                const uint32_t* bp = &Bs[(k0 + cc) * BS_STRIDE + bn0 + nt * 8];
                bf[nt][0] = bp[0];
                bf[nt][1] = bp[4 * BS_STRIDE];
            }

            #pragma unroll
            for (int mt = 0; mt < 2; mt++)
                #pragma unroll
                for (int nt = 0; nt < 4; nt++)
                    mma_16x8x8_tf32(acc[mt][nt], a[mt], bf[nt]);
        }

        // ---- epilogue: bias + tanh, float2 stores ----
        #pragma unroll
        for (int nt = 0; nt < 4; nt++) {
            const int col = wn * 32 + nt * 8 + 2 * cc;
            const float2 bj = *reinterpret_cast<const float2*>(&bs[col]);
            #pragma unroll
            for (int mt = 0; mt < 2; mt++) {
                const int row0 = wm * 32 + mt * 16 + g;
                const int edge0 = e0 + row0;
                if (edge0 < n_edges) {
                    float2 r;
                    r.x = tanhf(acc[mt][nt][0] + bj.x);
                    r.y = tanhf(acc[mt][nt][1] + bj.y);
                    *reinterpret_cast<float2*>(&out[(size_t)edge0 * N_DIM + col]) = r;
                }
                const int edge1 = edge0 + 8;
                if (edge1 < n_edges) {
                    float2 r;
                    r.x = tanhf(acc[mt][nt][2] + bj.x);
                    r.y = tanhf(acc[mt][nt][3] + bj.y);
                    *reinterpret_cast<float2*>(&out[(size_t)edge1 * N_DIM + col]) = r;
                }
            }
        }

        __syncthreads();   // compute done before this buffer is re-filled
        bufsel ^= 1;
    }
}

extern "C" void kernel_launch(void* const* d_in, const int* in_sizes, int n_in,
                              void* d_out, int out_size)
{
    const float* node_feats = (const float*)d_in[0];
    const int*   senders    = (const int*)d_in[1];
    const int*   receivers  = (const int*)d_in[2];
    const float* W          = (const float*)d_in[3];
    const float* b          = (const float*)d_in[4];
    float*       out        = (float*)d_out;

    const int n_edges = in_sizes[1];
    const int n_tiles = (n_edges + TILE_M - 1) / TILE_M;

    static int n_sms = 0;
    if (n_sms == 0) {   // host-side queries, cached; never executed during capture
        cudaFuncSetAttribute(noisenet_pipe_kernel,
                             cudaFuncAttributeMaxDynamicSharedMemorySize, SMEM_BYTES);
        int dev = 0;
        cudaGetDevice(&dev);
        cudaDeviceGetAttribute(&n_sms, cudaDevAttrMultiProcessorCount, dev);
        if (n_sms <= 0) n_sms = 148;
    }

    const int grid = (n_tiles < n_sms) ? n_tiles : n_sms;
    noisenet_pipe_kernel<<<grid, THREADS, SMEM_BYTES>>>(
        node_feats, senders, receivers, W, b, out, n_edges, n_tiles);
}

// round 5
// speedup vs baseline: 2.6952x; 1.3469x over previous
#include <cuda_runtime.h>
#include <cuda_bf16.h>
#include <cstdint>

// NoiseNet: out[e,:] = tanh( concat(nf[recv[e]], nf[send[e]]) @ W + b )
// E=800000, D=64 -> K=128, N=64.
// Persistent CTAs (2/SM), single-buffer cp.async gather with register index
// prefetch, warp-level mma.sync tf32.

#define K_DIM 128
#define N_DIM 64
#define TILE_M 128
#define THREADS 256
#define AS_STRIDE 132   // floats; 528B rows -> 16B aligned, conflict-free frags
#define BS_STRIDE 72    // floats; banks (8cc + g) unique per warp

#define A_BUF_FLOATS (TILE_M * AS_STRIDE)     // 16896 floats = 67584 B
#define B_FLOATS     (K_DIM * BS_STRIDE)      // 9216 floats  = 36864 B
#define SMEM_FLOATS  (A_BUF_FLOATS + B_FLOATS + N_DIM)
#define SMEM_BYTES   (SMEM_FLOATS * 4)        // 104704 B -> 2 CTAs/SM

__device__ __forceinline__ uint32_t smem_u32(const void* p) {
    uint32_t a;
    asm("{ .reg .u64 t; cvta.to.shared.u64 t, %1; cvt.u32.u64 %0, t; }" : "=r"(a) : "l"(p));
    return a;
}

__device__ __forceinline__ void cp16(uint32_t dst, const void* src) {
    asm volatile("cp.async.cg.shared.global.L2::128B [%0], [%1], 16;"
                 :: "r"(dst), "l"(src));
}
__device__ __forceinline__ void cp_commit() {
    asm volatile("cp.async.commit_group;" ::: "memory");
}
__device__ __forceinline__ void cp_wait0() {
    asm volatile("cp.async.wait_group 0;" ::: "memory");
}

__device__ __forceinline__ uint32_t f2tf32(float x) {
    uint32_t r;
    asm("cvt.rna.tf32.f32 %0, %1;" : "=r"(r) : "f"(x));
    return r;
}

__device__ __forceinline__ void mma_16x8x8_tf32(float c[4], const uint32_t a[4],
                                                const uint32_t b[2]) {
    asm volatile(
        "mma.sync.aligned.m16n8k8.row.col.f32.tf32.tf32.f32 "
        "{%0,%1,%2,%3}, {%4,%5,%6,%7}, {%8,%9}, {%0,%1,%2,%3};"
        : "+f"(c[0]), "+f"(c[1]), "+f"(c[2]), "+f"(c[3])
        : "r"(a[0]), "r"(a[1]), "r"(a[2]), "r"(a[3]), "r"(b[0]), "r"(b[1]));
}

__global__ __launch_bounds__(THREADS, 2)
void noisenet_pipe2_kernel(const float* __restrict__ node_feats,
                           const int* __restrict__ senders,
                           const int* __restrict__ receivers,
                           const float* __restrict__ W,
                           const float* __restrict__ bias,
                           float* __restrict__ out,
                           int n_edges, int n_tiles)
{
    extern __shared__ uint32_t smem[];
    uint32_t* As = smem;                               // [TILE_M][AS_STRIDE]
    uint32_t* Bs = smem + A_BUF_FLOATS;                // [K][BS_STRIDE] tf32
    float*    bs = reinterpret_cast<float*>(Bs + B_FLOATS);  // bias [64]

    const int tid = threadIdx.x;
    const int wid = tid >> 5;
    const int lid = tid & 31;
    const uint32_t a_addr = smem_u32(As);

    // ---- Stage B = W[128][64] (tf32 RNA) + bias ----
    {
        const float4* Wg = reinterpret_cast<const float4*>(W);
        #pragma unroll
        for (int c = tid; c < K_DIM * (N_DIM / 4); c += THREADS) {
            const int k  = c >> 4;
            const int n4 = c & 15;
            float4 v = Wg[c];
            uint32_t* dst = &Bs[k * BS_STRIDE + n4 * 4];
            dst[0] = f2tf32(v.x); dst[1] = f2tf32(v.y);
            dst[2] = f2tf32(v.z); dst[3] = f2tf32(v.w);
        }
        if (tid < N_DIM) bs[tid] = bias[tid];
    }

    // Gather geometry: thread covers edges e_base+8j (j=0..15) at float4 col q.
    const int e_base = tid >> 5;
    const int q      = tid & 31;
    const int* idx_src = (q < 16) ? receivers : senders;
    const int qoff   = (q & 15);
    const uint32_t dst_off = (uint32_t)(q * 16);
    const float4* nf4 = reinterpret_cast<const float4*>(node_feats);

    auto load_indices = [&](int tile, int* nodes) {
        const int e0 = tile * TILE_M;
        #pragma unroll
        for (int j = 0; j < 16; j++) {
            int edge = e0 + e_base + 8 * j;
            if (edge >= n_edges) edge = n_edges - 1;   // tail clamp
            nodes[j] = idx_src[edge];
        }
    };

    // fragment geometry
    const int wm = wid & 3;
    const int wn = wid >> 2;
    const int g  = lid >> 2;
    const int cc = lid & 3;
    const int arow0 = wm * 32 + g;
    const int bn0   = wn * 32 + g;

    int nodes[16];
    int tile = blockIdx.x;
    if (tile < n_tiles) load_indices(tile, nodes);

    for (; tile < n_tiles; tile += gridDim.x) {
        // ---- issue gather for this tile (indices already in regs) ----
        #pragma unroll
        for (int j = 0; j < 16; j++) {
            const int e = e_base + 8 * j;
            cp16(a_addr + (uint32_t)e * (AS_STRIDE * 4) + dst_off,
                 nf4 + (size_t)nodes[j] * 16 + qoff);
        }
        cp_commit();

        // ---- prefetch next tile's indices (overlaps cp.async + compute) ----
        const int next = tile + gridDim.x;
        if (next < n_tiles) load_indices(next, nodes);

        cp_wait0();
        __syncthreads();           // full A tile visible (and B on first iter)

        const int e0 = tile * TILE_M;

        float acc[2][4][4];
        #pragma unroll
        for (int mt = 0; mt < 2; mt++)
            #pragma unroll
            for (int nt = 0; nt < 4; nt++)
                #pragma unroll
                for (int r = 0; r < 4; r++)
                    acc[mt][nt][r] = 0.0f;

        #pragma unroll
        for (int s = 0; s < K_DIM / 8; s++) {
            const int k0 = s * 8;

            uint32_t a[2][4];
            #pragma unroll
            for (int mt = 0; mt < 2; mt++) {
                const uint32_t* ap = &As[(arow0 + mt * 16) * AS_STRIDE + k0 + cc];
                a[mt][0] = ap[0];
                a[mt][1] = ap[8 * AS_STRIDE];
                a[mt][2] = ap[4];
                a[mt][3] = ap[8 * AS_STRIDE + 4];
            }

            uint32_t bf[4][2];
            #pragma unroll
            for (int nt = 0; nt < 4; nt++) {
                const uint32_t* bp = &Bs[(k0 + cc) * BS_STRIDE + bn0 + nt * 8];
                bf[nt][0] = bp[0];
                bf[nt][1] = bp[4 * BS_STRIDE];
            }

            #pragma unroll
            for (int mt = 0; mt < 2; mt++)
                #pragma unroll
                for (int nt = 0; nt < 4; nt++)
                    mma_16x8x8_tf32(acc[mt][nt], a[mt], bf[nt]);
        }

        // ---- epilogue: bias + tanh, float2 stores ----
        #pragma unroll
        for (int nt = 0; nt < 4; nt++) {
            const int col = wn * 32 + nt * 8 + 2 * cc;
            const float2 bj = *reinterpret_cast<const float2*>(&bs[col]);
            #pragma unroll
            for (int mt = 0; mt < 2; mt++) {
                const int row0 = wm * 32 + mt * 16 + g;
                const int edge0 = e0 + row0;
                if (edge0 < n_edges) {
                    float2 r;
                    r.x = tanhf(acc[mt][nt][0] + bj.x);
                    r.y = tanhf(acc[mt][nt][1] + bj.y);
                    *reinterpret_cast<float2*>(&out[(size_t)edge0 * N_DIM + col]) = r;
                }
                const int edge1 = edge0 + 8;
                if (edge1 < n_edges) {
                    float2 r;
                    r.x = tanhf(acc[mt][nt][2] + bj.x);
                    r.y = tanhf(acc[mt][nt][3] + bj.y);
                    *reinterpret_cast<float2*>(&out[(size_t)edge1 * N_DIM + col]) = r;
                }
            }
        }

        __syncthreads();   // A fully consumed before next gather overwrites it
    }
}

extern "C" void kernel_launch(void* const* d_in, const int* in_sizes, int n_in,
                              void* d_out, int out_size)
{
    const float* node_feats = (const float*)d_in[0];
    const int*   senders    = (const int*)d_in[1];
    const int*   receivers  = (const int*)d_in[2];
    const float* W          = (const float*)d_in[3];
    const float* b          = (const float*)d_in[4];
    float*       out        = (float*)d_out;

    const int n_edges = in_sizes[1];
    const int n_tiles = (n_edges + TILE_M - 1) / TILE_M;

    static int n_sms = 0;
    if (n_sms == 0) {   // host-side setup, cached; never runs during capture
        cudaFuncSetAttribute(noisenet_pipe2_kernel,
                             cudaFuncAttributeMaxDynamicSharedMemorySize, SMEM_BYTES);
        int dev = 0;
        cudaGetDevice(&dev);
        cudaDeviceGetAttribute(&n_sms, cudaDevAttrMultiProcessorCount, dev);
        if (n_sms <= 0) n_sms = 148;
    }

    int grid = 2 * n_sms;
    if (grid > n_tiles) grid = n_tiles;
    noisenet_pipe2_kernel<<<grid, THREADS, SMEM_BYTES>>>(
        node_feats, senders, receivers, W, b, out, n_edges, n_tiles);
}

// round 6
// speedup vs baseline: 2.7226x; 1.0101x over previous
#include <cuda_runtime.h>
#include <cuda_bf16.h>
#include <cstdint>

// NoiseNet: out[e,:] = tanh( concat(nf[recv[e]], nf[send[e]]) @ W + b )
// E=800000, D=64 -> K=128, N=64.
// Persistent CTAs (2/SM), cp.async gather + reg index prefetch,
// ldmatrix-fed warp-level mma.sync tf32, tanh.approx epilogue.

#define K_DIM 128
#define N_DIM 64
#define TILE_M 128
#define THREADS 256
#define AS_STRIDE 132   // floats; 528B rows: 8 consecutive rows conflict-free
#define BT_STRIDE 132   // Bt[n][k] rows, same phase

#define A_BUF_FLOATS (TILE_M * AS_STRIDE)     // 16896 floats = 67584 B
#define BT_FLOATS    (N_DIM * BT_STRIDE)      // 8448 floats  = 33792 B
#define SMEM_FLOATS  (A_BUF_FLOATS + BT_FLOATS + N_DIM)
#define SMEM_BYTES   (SMEM_FLOATS * 4)        // 101632 B -> 2 CTAs/SM

__device__ __forceinline__ uint32_t smem_u32(const void* p) {
    uint32_t a;
    asm("{ .reg .u64 t; cvta.to.shared.u64 t, %1; cvt.u32.u64 %0, t; }" : "=r"(a) : "l"(p));
    return a;
}

__device__ __forceinline__ void cp16(uint32_t dst, const void* src) {
    asm volatile("cp.async.cg.shared.global.L2::128B [%0], [%1], 16;"
                 :: "r"(dst), "l"(src));
}
__device__ __forceinline__ void cp_commit() {
    asm volatile("cp.async.commit_group;" ::: "memory");
}
__device__ __forceinline__ void cp_wait0() {
    asm volatile("cp.async.wait_group 0;" ::: "memory");
}

__device__ __forceinline__ uint32_t f2tf32(float x) {
    uint32_t r;
    asm("cvt.rna.tf32.f32 %0, %1;" : "=r"(r) : "f"(x));
    return r;
}

__device__ __forceinline__ float tanh_fast(float x) {
    float y;
    asm("tanh.approx.f32 %0, %1;" : "=f"(y) : "f"(x));
    return y;
}

__device__ __forceinline__ void ldsm_x4(uint32_t& r0, uint32_t& r1,
                                        uint32_t& r2, uint32_t& r3, uint32_t addr) {
    asm volatile("ldmatrix.sync.aligned.m8n8.x4.shared.b16 {%0,%1,%2,%3}, [%4];"
                 : "=r"(r0), "=r"(r1), "=r"(r2), "=r"(r3) : "r"(addr));
}

__device__ __forceinline__ void mma_16x8x8_tf32(float c[4], const uint32_t a[4],
                                                const uint32_t b[2]) {
    asm volatile(
        "mma.sync.aligned.m16n8k8.row.col.f32.tf32.tf32.f32 "
        "{%0,%1,%2,%3}, {%4,%5,%6,%7}, {%8,%9}, {%0,%1,%2,%3};"
        : "+f"(c[0]), "+f"(c[1]), "+f"(c[2]), "+f"(c[3])
        : "r"(a[0]), "r"(a[1]), "r"(a[2]), "r"(a[3]), "r"(b[0]), "r"(b[1]));
}

__global__ __launch_bounds__(THREADS, 2)
void noisenet_ldsm_kernel(const float* __restrict__ node_feats,
                          const int* __restrict__ senders,
                          const int* __restrict__ receivers,
                          const float* __restrict__ W,
                          const float* __restrict__ bias,
                          float* __restrict__ out,
                          int n_edges, int n_tiles)
{
    extern __shared__ uint32_t smem[];
    uint32_t* As = smem;                         // [TILE_M][AS_STRIDE] f32/tf32
    uint32_t* Bt = smem + A_BUF_FLOATS;          // [N_DIM][BT_STRIDE] tf32 (n-major)
    float*    bs = reinterpret_cast<float*>(Bt + BT_FLOATS);  // bias [64]

    const int tid = threadIdx.x;
    const int wid = tid >> 5;
    const int lid = tid & 31;
    const uint32_t a_addr  = smem_u32(As);
    const uint32_t bt_addr = smem_u32(Bt);

    // ---- Stage Bt[n][k] = tf32(W[k][n]) (transpose; one-time, cached) ----
    {
        #pragma unroll
        for (int c = tid; c < N_DIM * (K_DIM / 4); c += THREADS) {
            const int n  = c >> 5;      // 0..63
            const int k4 = c & 31;      // float4 along k
            uint32_t* dst = &Bt[n * BT_STRIDE + k4 * 4];
            dst[0] = f2tf32(W[(k4 * 4 + 0) * N_DIM + n]);
            dst[1] = f2tf32(W[(k4 * 4 + 1) * N_DIM + n]);
            dst[2] = f2tf32(W[(k4 * 4 + 2) * N_DIM + n]);
            dst[3] = f2tf32(W[(k4 * 4 + 3) * N_DIM + n]);
        }
        if (tid < N_DIM) bs[tid] = bias[tid];
    }

    // Gather geometry: thread covers edges e_base+8j (j=0..15) at float4 col q.
    const int e_base = tid >> 5;
    const int q      = tid & 31;
    const int* idx_src = (q < 16) ? receivers : senders;
    const int qoff   = (q & 15);
    const uint32_t dst_off = (uint32_t)(q * 16);
    const float4* nf4 = reinterpret_cast<const float4*>(node_feats);

    auto load_indices = [&](int tile, int* nodes) {
        const int e0 = tile * TILE_M;
        #pragma unroll
        for (int j = 0; j < 16; j++) {
            int edge = e0 + e_base + 8 * j;
            if (edge >= n_edges) edge = n_edges - 1;   // tail clamp
            nodes[j] = idx_src[edge];
        }
    };

    // Warp tiling: warp (wm, wn) owns rows [32*wm,+32), cols [32*wn,+32)
    const int wm = wid & 3;
    const int wn = wid >> 2;
    const int g  = lid >> 2;      // 0..7
    const int cc = lid & 3;       // 0..3
    const int r16 = lid & 15;     // ldmatrix row within 16
    const int sel = (lid >> 4);   // 0: k-group k0, 1: k-group k0+4

    // ldmatrix base addresses (advance by 32B per k-step)
    uint32_t aF[2], bF[2];
    #pragma unroll
    for (int mt = 0; mt < 2; mt++)
        aF[mt] = a_addr + (uint32_t)((wm * 32 + mt * 16 + r16) * AS_STRIDE) * 4u
               + (uint32_t)sel * 16u;
    #pragma unroll
    for (int p = 0; p < 2; p++)
        bF[p] = bt_addr + (uint32_t)((wn * 32 + p * 16 + r16) * BT_STRIDE) * 4u
              + (uint32_t)sel * 16u;

    int nodes[16];
    int tile = blockIdx.x;
    if (tile < n_tiles) load_indices(tile, nodes);

    for (; tile < n_tiles; tile += gridDim.x) {
        // ---- issue gather (indices already in regs) ----
        #pragma unroll
        for (int j = 0; j < 16; j++) {
            const int e = e_base + 8 * j;
            cp16(a_addr + (uint32_t)e * (AS_STRIDE * 4) + dst_off,
                 nf4 + (size_t)nodes[j] * 16 + qoff);
        }
        cp_commit();

        // ---- prefetch next tile's indices ----
        const int next = tile + gridDim.x;
        if (next < n_tiles) load_indices(next, nodes);

        cp_wait0();
        __syncthreads();

        const int e0 = tile * TILE_M;

        float acc[2][4][4];
        #pragma unroll
        for (int mt = 0; mt < 2; mt++)
            #pragma unroll
            for (int nt = 0; nt < 4; nt++)
                #pragma unroll
                for (int r = 0; r < 4; r++)
                    acc[mt][nt][r] = 0.0f;

        #pragma unroll
        for (int s = 0; s < K_DIM / 8; s++) {
            const uint32_t koff = (uint32_t)s * 32u;

            uint32_t a[2][4];
            #pragma unroll
            for (int mt = 0; mt < 2; mt++)
                ldsm_x4(a[mt][0], a[mt][1], a[mt][2], a[mt][3], aF[mt] + koff);

            // B x4 per 16-row pair p: r0=b0(nt=2p), r1=b0(nt=2p+1),
            //                         r2=b1(nt=2p), r3=b1(nt=2p+1)
            uint32_t bf[4][2];
            #pragma unroll
            for (int p = 0; p < 2; p++) {
                uint32_t r0, r1, r2, r3;
                ldsm_x4(r0, r1, r2, r3, bF[p] + koff);
                bf[2 * p + 0][0] = r0; bf[2 * p + 0][1] = r2;
                bf[2 * p + 1][0] = r1; bf[2 * p + 1][1] = r3;
            }

            #pragma unroll
            for (int mt = 0; mt < 2; mt++)
                #pragma unroll
                for (int nt = 0; nt < 4; nt++)
                    mma_16x8x8_tf32(acc[mt][nt], a[mt], bf[nt]);
        }

        // ---- epilogue: bias + tanh.approx, float2 stores ----
        #pragma unroll
        for (int nt = 0; nt < 4; nt++) {
            const int col = wn * 32 + nt * 8 + 2 * cc;
            const float2 bj = *reinterpret_cast<const float2*>(&bs[col]);
            #pragma unroll
            for (int mt = 0; mt < 2; mt++) {
                const int row0 = wm * 32 + mt * 16 + g;
                const int edge0 = e0 + row0;
                if (edge0 < n_edges) {
                    float2 r;
                    r.x = tanh_fast(acc[mt][nt][0] + bj.x);
                    r.y = tanh_fast(acc[mt][nt][1] + bj.y);
                    *reinterpret_cast<float2*>(&out[(size_t)edge0 * N_DIM + col]) = r;
                }
                const int edge1 = edge0 + 8;
                if (edge1 < n_edges) {
                    float2 r;
                    r.x = tanh_fast(acc[mt][nt][2] + bj.x);
                    r.y = tanh_fast(acc[mt][nt][3] + bj.y);
                    *reinterpret_cast<float2*>(&out[(size_t)edge1 * N_DIM + col]) = r;
                }
            }
        }

        __syncthreads();   // A consumed before next gather overwrites it
    }
}

extern "C" void kernel_launch(void* const* d_in, const int* in_sizes, int n_in,
                              void* d_out, int out_size)
{
    const float* node_feats = (const float*)d_in[0];
    const int*   senders    = (const int*)d_in[1];
    const int*   receivers  = (const int*)d_in[2];
    const float* W          = (const float*)d_in[3];
    const float* b          = (const float*)d_in[4];
    float*       out        = (float*)d_out;

    const int n_edges = in_sizes[1];
    const int n_tiles = (n_edges + TILE_M - 1) / TILE_M;

    static int n_sms = 0;
    if (n_sms == 0) {   // host-side setup, cached; never runs during capture
        cudaFuncSetAttribute(noisenet_ldsm_kernel,
                             cudaFuncAttributeMaxDynamicSharedMemorySize, SMEM_BYTES);
        int dev = 0;
        cudaGetDevice(&dev);
        cudaDeviceGetAttribute(&n_sms, cudaDevAttrMultiProcessorCount, dev);
        if (n_sms <= 0) n_sms = 148;
    }

    int grid = 2 * n_sms;
    if (grid > n_tiles) grid = n_tiles;
    noisenet_ldsm_kernel<<<grid, THREADS, SMEM_BYTES>>>(
        node_feats, senders, receivers, W, b, out, n_edges, n_tiles);
}

// round 7
// speedup vs baseline: 2.8501x; 1.0469x over previous
#include <cuda_runtime.h>
#include <cuda_bf16.h>
#include <cstdint>

// NoiseNet: out[e,:] = tanh( concat(nf[recv[e]], nf[send[e]]) @ W + b )
// E=800000, D=64 -> K=128, N=64.
// Persistent CTAs (2/SM), TILE_M=64, double-buffered cp.async gather,
// B fragments register-resident for CTA lifetime, mma.sync tf32, tanh.approx.

#define K_DIM 128
#define N_DIM 64
#define TILE_M 64
#define THREADS 256
#define AS_STRIDE 132   // floats; 528B rows: consecutive rows conflict-free
#define BT_STRIDE 132

#define A_BUF_FLOATS (TILE_M * AS_STRIDE)     // 8448 floats = 33792 B per buf
#define BT_FLOATS    (N_DIM * BT_STRIDE)      // 8448 floats = 33792 B
#define SMEM_FLOATS  (2 * A_BUF_FLOATS + BT_FLOATS + N_DIM)
#define SMEM_BYTES   (SMEM_FLOATS * 4)        // 101632 B -> 2 CTAs/SM

__device__ __forceinline__ uint32_t smem_u32(const void* p) {
    uint32_t a;
    asm("{ .reg .u64 t; cvta.to.shared.u64 t, %1; cvt.u32.u64 %0, t; }" : "=r"(a) : "l"(p));
    return a;
}

__device__ __forceinline__ void cp16(uint32_t dst, const void* src) {
    asm volatile("cp.async.cg.shared.global.L2::128B [%0], [%1], 16;"
                 :: "r"(dst), "l"(src));
}
__device__ __forceinline__ void cp_commit() {
    asm volatile("cp.async.commit_group;" ::: "memory");
}
__device__ __forceinline__ void cp_wait1() {
    asm volatile("cp.async.wait_group 1;" ::: "memory");
}
__device__ __forceinline__ void cp_wait0() {
    asm volatile("cp.async.wait_group 0;" ::: "memory");
}

__device__ __forceinline__ uint32_t f2tf32(float x) {
    uint32_t r;
    asm("cvt.rna.tf32.f32 %0, %1;" : "=r"(r) : "f"(x));
    return r;
}

__device__ __forceinline__ float tanh_fast(float x) {
    float y;
    asm("tanh.approx.f32 %0, %1;" : "=f"(y) : "f"(x));
    return y;
}

__device__ __forceinline__ void ldsm_x4(uint32_t& r0, uint32_t& r1,
                                        uint32_t& r2, uint32_t& r3, uint32_t addr) {
    asm volatile("ldmatrix.sync.aligned.m8n8.x4.shared.b16 {%0,%1,%2,%3}, [%4];"
                 : "=r"(r0), "=r"(r1), "=r"(r2), "=r"(r3) : "r"(addr));
}

__device__ __forceinline__ void mma_16x8x8_tf32(float c[4], const uint32_t a[4],
                                                const uint32_t b0, const uint32_t b1) {
    asm volatile(
        "mma.sync.aligned.m16n8k8.row.col.f32.tf32.tf32.f32 "
        "{%0,%1,%2,%3}, {%4,%5,%6,%7}, {%8,%9}, {%0,%1,%2,%3};"
        : "+f"(c[0]), "+f"(c[1]), "+f"(c[2]), "+f"(c[3])
        : "r"(a[0]), "r"(a[1]), "r"(a[2]), "r"(a[3]), "r"(b0), "r"(b1));
}

__global__ __launch_bounds__(THREADS, 2)
void noisenet_breg_kernel(const float* __restrict__ node_feats,
                          const int* __restrict__ senders,
                          const int* __restrict__ receivers,
                          const float* __restrict__ W,
                          const float* __restrict__ bias,
                          float* __restrict__ out,
                          int n_edges, int n_tiles)
{
    extern __shared__ uint32_t smem[];
    uint32_t* A0 = smem;                          // buf 0
    uint32_t* A1 = smem + A_BUF_FLOATS;           // buf 1
    uint32_t* Bt = smem + 2 * A_BUF_FLOATS;       // [N][BT_STRIDE] tf32 n-major
    float*    bs = reinterpret_cast<float*>(Bt + BT_FLOATS);

    const int tid = threadIdx.x;
    const int wid = tid >> 5;
    const int lid = tid & 31;
    const uint32_t a0_addr = smem_u32(A0);
    const uint32_t a1_addr = smem_u32(A1);
    const uint32_t bt_addr = smem_u32(Bt);

    // ---- Stage Bt[n][k] = tf32(W[k][n]) + bias (one-time) ----
    {
        #pragma unroll
        for (int c = tid; c < N_DIM * (K_DIM / 4); c += THREADS) {
            const int n  = c >> 5;
            const int k4 = c & 31;
            uint32_t* dst = &Bt[n * BT_STRIDE + k4 * 4];
            dst[0] = f2tf32(W[(k4 * 4 + 0) * N_DIM + n]);
            dst[1] = f2tf32(W[(k4 * 4 + 1) * N_DIM + n]);
            dst[2] = f2tf32(W[(k4 * 4 + 2) * N_DIM + n]);
            dst[3] = f2tf32(W[(k4 * 4 + 3) * N_DIM + n]);
        }
        if (tid < N_DIM) bs[tid] = bias[tid];
    }
    __syncthreads();

    // Warp tiling: wm in {0,1} -> rows 32*wm..+32; wn in {0..3} -> cols 16*wn..+16
    const int wm = wid & 1;
    const int wn = wid >> 1;
    const int g  = lid >> 2;
    const int cc = lid & 3;
    const int r16 = lid & 15;
    const int sel = lid >> 4;

    // ---- Load B fragments into registers (CTA lifetime) ----
    // breg[s][nt][j]: nt in {0,1} (8 cols each), j = k-reg
    uint32_t breg[16][2][2];
    {
        const uint32_t bF = bt_addr
            + (uint32_t)((wn * 16 + r16) * BT_STRIDE) * 4u + (uint32_t)sel * 16u;
        #pragma unroll
        for (int s = 0; s < 16; s++) {
            uint32_t r0, r1, r2, r3;
            ldsm_x4(r0, r1, r2, r3, bF + (uint32_t)s * 32u);
            breg[s][0][0] = r0; breg[s][1][0] = r1;
            breg[s][0][1] = r2; breg[s][1][1] = r3;
        }
    }

    // Gather geometry: thread covers edges e_base+8j (j=0..7) at float4 col q.
    const int e_base = tid >> 5;
    const int q      = tid & 31;
    const int* idx_src = (q < 16) ? receivers : senders;
    const int qoff   = (q & 15);
    const uint32_t dst_off = (uint32_t)(q * 16);
    const float4* nf4 = reinterpret_cast<const float4*>(node_feats);

    // A fragment row offsets (per mt), relative to buffer base
    uint32_t aOff[2];
    #pragma unroll
    for (int mt = 0; mt < 2; mt++)
        aOff[mt] = (uint32_t)((wm * 32 + mt * 16 + r16) * AS_STRIDE) * 4u
                 + (uint32_t)sel * 16u;

    auto issue_gather = [&](int tile, uint32_t abuf, int* nodes) {
        const int e0 = tile * TILE_M;
        #pragma unroll
        for (int j = 0; j < 8; j++) {
            int edge = e0 + e_base + 8 * j;
            if (edge >= n_edges) edge = n_edges - 1;
            nodes[j] = idx_src[edge];
        }
        #pragma unroll
        for (int j = 0; j < 8; j++) {
            const int e = e_base + 8 * j;
            cp16(abuf + (uint32_t)e * (AS_STRIDE * 4) + dst_off,
                 nf4 + (size_t)nodes[j] * 16 + qoff);
        }
        cp_commit();
    };

    int nodes[8];
    int tile = blockIdx.x;
    if (tile < n_tiles) issue_gather(tile, a0_addr, nodes);

    int parity = 0;
    for (; tile < n_tiles; tile += gridDim.x) {
        const int next = tile + gridDim.x;
        if (next < n_tiles) {
            issue_gather(next, parity ? a0_addr : a1_addr, nodes);
            cp_wait1();
        } else {
            cp_wait0();
        }
        __syncthreads();

        const uint32_t abuf = parity ? a1_addr : a0_addr;
        const int e0 = tile * TILE_M;

        float acc[2][2][4];
        #pragma unroll
        for (int mt = 0; mt < 2; mt++)
            #pragma unroll
            for (int nt = 0; nt < 2; nt++)
                #pragma unroll
                for (int r = 0; r < 4; r++)
                    acc[mt][nt][r] = 0.0f;

        #pragma unroll
        for (int s = 0; s < 16; s++) {
            const uint32_t koff = (uint32_t)s * 32u;
            #pragma unroll
            for (int mt = 0; mt < 2; mt++) {
                uint32_t a[4];
                ldsm_x4(a[0], a[1], a[2], a[3], abuf + aOff[mt] + koff);
                mma_16x8x8_tf32(acc[mt][0], a, breg[s][0][0], breg[s][0][1]);
                mma_16x8x8_tf32(acc[mt][1], a, breg[s][1][0], breg[s][1][1]);
            }
        }

        // ---- epilogue: bias + tanh.approx, float2 stores ----
        #pragma unroll
        for (int nt = 0; nt < 2; nt++) {
            const int col = wn * 16 + nt * 8 + 2 * cc;
            const float2 bj = *reinterpret_cast<const float2*>(&bs[col]);
            #pragma unroll
            for (int mt = 0; mt < 2; mt++) {
                const int edge0 = e0 + wm * 32 + mt * 16 + g;
                if (edge0 < n_edges) {
                    float2 r;
                    r.x = tanh_fast(acc[mt][nt][0] + bj.x);
                    r.y = tanh_fast(acc[mt][nt][1] + bj.y);
                    *reinterpret_cast<float2*>(&out[(size_t)edge0 * N_DIM + col]) = r;
                }
                const int edge1 = edge0 + 8;
                if (edge1 < n_edges) {
                    float2 r;
                    r.x = tanh_fast(acc[mt][nt][2] + bj.x);
                    r.y = tanh_fast(acc[mt][nt][3] + bj.y);
                    *reinterpret_cast<float2*>(&out[(size_t)edge1 * N_DIM + col]) = r;
                }
            }
        }

        __syncthreads();   // this tile's buffer free before it is re-filled
        parity ^= 1;
    }
}

extern "C" void kernel_launch(void* const* d_in, const int* in_sizes, int n_in,
                              void* d_out, int out_size)
{
    const float* node_feats = (const float*)d_in[0];
    const int*   senders    = (const int*)d_in[1];
    const int*   receivers  = (const int*)d_in[2];
    const float* W          = (const float*)d_in[3];
    const float* b          = (const float*)d_in[4];
    float*       out        = (float*)d_out;

    const int n_edges = in_sizes[1];
    const int n_tiles = (n_edges + TILE_M - 1) / TILE_M;

    static int n_sms = 0;
    if (n_sms == 0) {   // host-side setup, cached; never runs during capture
        cudaFuncSetAttribute(noisenet_breg_kernel,
                             cudaFuncAttributeMaxDynamicSharedMemorySize, SMEM_BYTES);
        int dev = 0;
        cudaGetDevice(&dev);
        cudaDeviceGetAttribute(&n_sms, cudaDevAttrMultiProcessorCount, dev);
        if (n_sms <= 0) n_sms = 148;
    }

    int grid = 2 * n_sms;
    if (grid > n_tiles) grid = n_tiles;
    noisenet_breg_kernel<<<grid, THREADS, SMEM_BYTES>>>(
        node_feats, senders, receivers, W, b, out, n_edges, n_tiles);
}

// round 8
// speedup vs baseline: 4.1036x; 1.4398x over previous
#include <cuda_runtime.h>
#include <cuda_fp16.h>
#include <cstdint>

// NoiseNet: out[e,:] = tanh( concat(nf[recv[e]], nf[send[e]]) @ W + b )
// E=800000, D=64 -> K=128, N=64.
// fp16 datapath: pre-converted node feats (fp16), cp.async gather,
// mma.m16n8k16.f16 with register-resident B, tanh.approx, 3 CTAs/SM.

#define K_DIM 128
#define N_DIM 64
#define TILE_M 64
#define THREADS 256
#define NF_ELEMS (50000 * 64)

#define A_ROW_BYTES 272      // 128 halfs (256B) + 16B pad: conflict-free LDSM
#define B_ROW_BYTES 272
#define A_BUF_BYTES (TILE_M * A_ROW_BYTES)    // 17408
#define B_BUF_BYTES (N_DIM * B_ROW_BYTES)     // 17408
#define SMEM_BYTES  (2 * A_BUF_BYTES + B_BUF_BYTES)   // 52224 -> 3 CTAs/SM

__device__ __half g_nf_h[NF_ELEMS];

__global__ void convert_nf_kernel(const float* __restrict__ nf, int n2) {
    int i = blockIdx.x * blockDim.x + threadIdx.x;
    if (i < n2) {
        float2 v = reinterpret_cast<const float2*>(nf)[i];
        reinterpret_cast<__half2*>(g_nf_h)[i] = __floats2half2_rn(v.x, v.y);
    }
}

__device__ __forceinline__ uint32_t smem_u32(const void* p) {
    uint32_t a;
    asm("{ .reg .u64 t; cvta.to.shared.u64 t, %1; cvt.u32.u64 %0, t; }" : "=r"(a) : "l"(p));
    return a;
}
__device__ __forceinline__ void cp16(uint32_t dst, const void* src) {
    asm volatile("cp.async.cg.shared.global.L2::128B [%0], [%1], 16;"
                 :: "r"(dst), "l"(src));
}
__device__ __forceinline__ void cp_commit() {
    asm volatile("cp.async.commit_group;" ::: "memory");
}
__device__ __forceinline__ void cp_wait1() {
    asm volatile("cp.async.wait_group 1;" ::: "memory");
}
__device__ __forceinline__ void cp_wait0() {
    asm volatile("cp.async.wait_group 0;" ::: "memory");
}
__device__ __forceinline__ float tanh_fast(float x) {
    float y;
    asm("tanh.approx.f32 %0, %1;" : "=f"(y) : "f"(x));
    return y;
}
__device__ __forceinline__ void ldsm_x4(uint32_t& r0, uint32_t& r1,
                                        uint32_t& r2, uint32_t& r3, uint32_t addr) {
    asm volatile("ldmatrix.sync.aligned.m8n8.x4.shared.b16 {%0,%1,%2,%3}, [%4];"
                 : "=r"(r0), "=r"(r1), "=r"(r2), "=r"(r3) : "r"(addr));
}
__device__ __forceinline__ void mma_16x8x16_f16(float c[4], const uint32_t a[4],
                                                uint32_t b0, uint32_t b1) {
    asm volatile(
        "mma.sync.aligned.m16n8k16.row.col.f32.f16.f16.f32 "
        "{%0,%1,%2,%3}, {%4,%5,%6,%7}, {%8,%9}, {%0,%1,%2,%3};"
        : "+f"(c[0]), "+f"(c[1]), "+f"(c[2]), "+f"(c[3])
        : "r"(a[0]), "r"(a[1]), "r"(a[2]), "r"(a[3]), "r"(b0), "r"(b1));
}

__global__ __launch_bounds__(THREADS, 3)
void noisenet_fp16_kernel(const int* __restrict__ senders,
                          const int* __restrict__ receivers,
                          const float* __restrict__ W,
                          const float* __restrict__ bias,
                          float* __restrict__ out,
                          int n_edges, int n_tiles)
{
    extern __shared__ char smem[];
    char* A0 = smem;
    char* A1 = smem + A_BUF_BYTES;
    char* Bt = smem + 2 * A_BUF_BYTES;   // [N][128 halfs] n-major fp16

    const int tid = threadIdx.x;
    const int wid = tid >> 5;
    const int lid = tid & 31;
    const uint32_t a0_addr = smem_u32(A0);
    const uint32_t a1_addr = smem_u32(A1);
    const uint32_t bt_addr = smem_u32(Bt);

    // ---- Stage Bt[n][k] = fp16(W[k][n]) (one-time transpose) ----
    for (int c = tid; c < N_DIM * 16; c += THREADS) {
        const int n  = c >> 4;
        const int kq = c & 15;              // 8-half granule along k
        __half2 h[4];
        #pragma unroll
        for (int j = 0; j < 4; j++)
            h[j] = __floats2half2_rn(W[(kq * 8 + 2 * j) * N_DIM + n],
                                     W[(kq * 8 + 2 * j + 1) * N_DIM + n]);
        *reinterpret_cast<uint4*>(Bt + n * B_ROW_BYTES + kq * 16)
            = *reinterpret_cast<uint4*>(h);
    }
    __syncthreads();

    // Warp tiling: wm in {0,1} rows 32*wm..+32; wn in {0..3} cols 16*wn..+16
    const int wm = wid & 1;
    const int wn = wid >> 1;
    const int g  = lid >> 2;
    const int cc = lid & 3;

    // ---- B fragments -> registers (CTA lifetime): 8 k-steps x 2 nt x 2 ----
    uint32_t breg[8][2][2];
    {
        const int n_lane = wn * 16 + ((lid >> 4) & 1) * 8 + (lid & 7);
        const uint32_t koff16 = (uint32_t)(((lid >> 3) & 1) * 16);
        const uint32_t bF = bt_addr + (uint32_t)n_lane * B_ROW_BYTES + koff16;
        #pragma unroll
        for (int s = 0; s < 8; s++) {
            uint32_t r0, r1, r2, r3;
            ldsm_x4(r0, r1, r2, r3, bF + (uint32_t)s * 32u);
            breg[s][0][0] = r0; breg[s][0][1] = r1;   // nt0: b0, b1
            breg[s][1][0] = r2; breg[s][1][1] = r3;   // nt1: b0, b1
        }
    }

    // bias -> registers (cols fixed per thread across all tiles)
    float2 bj[2];
    #pragma unroll
    for (int nt = 0; nt < 2; nt++)
        bj[nt] = *reinterpret_cast<const float2*>(&bias[wn * 16 + nt * 8 + 2 * cc]);

    // Gather geometry: q = 16B granule within edge (0..15), e_base = tid>>4.
    // Edge row: recv 8 granules (q<8) then send 8 granules.
    const int e_base = tid >> 4;
    const int q      = tid & 15;
    const int* idx_src = (q < 8) ? receivers : senders;
    const int qoff   = (q & 7);                      // granule within node row
    const uint32_t dst_off = (uint32_t)(q * 16);
    const char* nf_bytes = reinterpret_cast<const char*>(g_nf_h);

    auto issue_gather = [&](int tile, uint32_t abuf, int* nodes) {
        const int e0 = tile * TILE_M;
        #pragma unroll
        for (int j = 0; j < 4; j++) {
            int edge = e0 + e_base + 16 * j;
            if (edge >= n_edges) edge = n_edges - 1;
            nodes[j] = idx_src[edge];
        }
        #pragma unroll
        for (int j = 0; j < 4; j++) {
            const int e = e_base + 16 * j;
            cp16(abuf + (uint32_t)e * A_ROW_BYTES + dst_off,
                 nf_bytes + (size_t)nodes[j] * 128 + qoff * 16);
        }
        cp_commit();
    };

    // A fragment addresses (per mt), relative to buffer base
    uint32_t aOff[2];
    #pragma unroll
    for (int mt = 0; mt < 2; mt++)
        aOff[mt] = (uint32_t)((wm * 32 + mt * 16 + (lid & 15)) * A_ROW_BYTES)
                 + (uint32_t)((lid >> 4) * 16);

    int nodes[4];
    int tile = blockIdx.x;
    if (tile < n_tiles) issue_gather(tile, a0_addr, nodes);

    int parity = 0;
    for (; tile < n_tiles; tile += gridDim.x) {
        const int next = tile + gridDim.x;
        if (next < n_tiles) {
            issue_gather(next, parity ? a0_addr : a1_addr, nodes);
            cp_wait1();
        } else {
            cp_wait0();
        }
        __syncthreads();

        const uint32_t abuf = parity ? a1_addr : a0_addr;
        const int e0 = tile * TILE_M;

        float acc[2][2][4];
        #pragma unroll
        for (int mt = 0; mt < 2; mt++)
            #pragma unroll
            for (int nt = 0; nt < 2; nt++)
                #pragma unroll
                for (int r = 0; r < 4; r++)
                    acc[mt][nt][r] = 0.0f;

        #pragma unroll
        for (int s = 0; s < 8; s++) {
            const uint32_t koff = (uint32_t)s * 32u;   // 16 halfs per step
            #pragma unroll
            for (int mt = 0; mt < 2; mt++) {
                uint32_t a[4];
                ldsm_x4(a[0], a[1], a[2], a[3], abuf + aOff[mt] + koff);
                mma_16x8x16_f16(acc[mt][0], a, breg[s][0][0], breg[s][0][1]);
                mma_16x8x16_f16(acc[mt][1], a, breg[s][1][0], breg[s][1][1]);
            }
        }

        // ---- epilogue: bias + tanh.approx, float2 stores ----
        #pragma unroll
        for (int nt = 0; nt < 2; nt++) {
            const int col = wn * 16 + nt * 8 + 2 * cc;
            #pragma unroll
            for (int mt = 0; mt < 2; mt++) {
                const int edge0 = e0 + wm * 32 + mt * 16 + g;
                if (edge0 < n_edges) {
                    float2 r;
                    r.x = tanh_fast(acc[mt][nt][0] + bj[nt].x);
                    r.y = tanh_fast(acc[mt][nt][1] + bj[nt].y);
                    *reinterpret_cast<float2*>(&out[(size_t)edge0 * N_DIM + col]) = r;
                }
                const int edge1 = edge0 + 8;
                if (edge1 < n_edges) {
                    float2 r;
                    r.x = tanh_fast(acc[mt][nt][2] + bj[nt].x);
                    r.y = tanh_fast(acc[mt][nt][3] + bj[nt].y);
                    *reinterpret_cast<float2*>(&out[(size_t)edge1 * N_DIM + col]) = r;
                }
            }
        }

        __syncthreads();   // buffer consumed before refill
        parity ^= 1;
    }
}

extern "C" void kernel_launch(void* const* d_in, const int* in_sizes, int n_in,
                              void* d_out, int out_size)
{
    const float* node_feats = (const float*)d_in[0];
    const int*   senders    = (const int*)d_in[1];
    const int*   receivers  = (const int*)d_in[2];
    const float* W          = (const float*)d_in[3];
    const float* b          = (const float*)d_in[4];
    float*       out        = (float*)d_out;

    const int n_feat  = in_sizes[0];
    const int n_edges = in_sizes[1];
    const int n_tiles = (n_edges + TILE_M - 1) / TILE_M;

    static int n_sms = 0;
    if (n_sms == 0) {   // host-side setup, cached; never runs during capture
        cudaFuncSetAttribute(noisenet_fp16_kernel,
                             cudaFuncAttributeMaxDynamicSharedMemorySize, SMEM_BYTES);
        int dev = 0;
        cudaGetDevice(&dev);
        cudaDeviceGetAttribute(&n_sms, cudaDevAttrMultiProcessorCount, dev);
        if (n_sms <= 0) n_sms = 148;
    }

    const int n2 = n_feat / 2;
    convert_nf_kernel<<<(n2 + 255) / 256, 256>>>(node_feats, n2);

    int grid = 3 * n_sms;
    if (grid > n_tiles) grid = n_tiles;
    noisenet_fp16_kernel<<<grid, THREADS, SMEM_BYTES>>>(
        senders, receivers, W, b, out, n_edges, n_tiles);
}

// round 9
// speedup vs baseline: 4.6436x; 1.1316x over previous
#include <cuda_runtime.h>
#include <cuda_fp16.h>
#include <cstdint>

// NoiseNet: out[e,:] = tanh( concat(nf[recv[e]], nf[send[e]]) @ W + b )
// Factored:  P[n][0:64]  = nf[n] @ W[0:64,:]  + b   (recv table, bias folded)
//            P[n][64:128]= nf[n] @ W[64:128,:]      (send table)
//            out[e]      = tanh( P[recv[e]][0:64] + P[send[e]][64:128] )
// Precompute: one 50000x128 (K=64) fp16 tensor-core GEMM.
// Edge kernel: pure gather + add + tanh + store (no smem, no barriers).

#define D_FEAT 64
#define P_COLS 128
#define MAX_NODES 50000

#define PM 128              // nodes per precompute CTA
#define ROW_B 144           // 64 halfs (128B) + 16B pad: conflict-free LDSM
#define PRE_SMEM (2 * PM * ROW_B)   // A tile + Bt tile

__device__ float g_P[MAX_NODES * P_COLS];   // 25.6 MB node table

__device__ __forceinline__ uint32_t smem_u32(const void* p) {
    uint32_t a;
    asm("{ .reg .u64 t; cvta.to.shared.u64 t, %1; cvt.u32.u64 %0, t; }" : "=r"(a) : "l"(p));
    return a;
}
__device__ __forceinline__ float tanh_fast(float x) {
    float y;
    asm("tanh.approx.f32 %0, %1;" : "=f"(y) : "f"(x));
    return y;
}
__device__ __forceinline__ void ldsm_x4(uint32_t& r0, uint32_t& r1,
                                        uint32_t& r2, uint32_t& r3, uint32_t addr) {
    asm volatile("ldmatrix.sync.aligned.m8n8.x4.shared.b16 {%0,%1,%2,%3}, [%4];"
                 : "=r"(r0), "=r"(r1), "=r"(r2), "=r"(r3) : "r"(addr));
}
__device__ __forceinline__ void mma_16x8x16_f16(float c[4], const uint32_t a[4],
                                                uint32_t b0, uint32_t b1) {
    asm volatile(
        "mma.sync.aligned.m16n8k16.row.col.f32.f16.f16.f32 "
        "{%0,%1,%2,%3}, {%4,%5,%6,%7}, {%8,%9}, {%0,%1,%2,%3};"
        : "+f"(c[0]), "+f"(c[1]), "+f"(c[2]), "+f"(c[3])
        : "r"(a[0]), "r"(a[1]), "r"(a[2]), "r"(a[3]), "r"(b0), "r"(b1));
}

// ---- Precompute: P[m0..m0+128][128] = nf @ [Wtop | Wbot]  (+bias on cols<64) ----
__global__ __launch_bounds__(256)
void precompute_P_kernel(const float* __restrict__ nf,
                         const float* __restrict__ W,
                         const float* __restrict__ bias,
                         int n_nodes)
{
    extern __shared__ char smem[];
    char* As = smem;                    // [128 rows][ROW_B]  fp16 node feats
    char* Bt = smem + PM * ROW_B;       // [128 n][ROW_B]     fp16 Wcat, n-major

    const int tid = threadIdx.x;
    const int wid = tid >> 5;
    const int lid = tid & 31;
    const int m0  = blockIdx.x * PM;
    const uint32_t a_addr  = smem_u32(As);
    const uint32_t bt_addr = smem_u32(Bt);

    // Stage Bt[n][k]: n<64 -> W[k][n]; n>=64 -> W[64+k][n-64]
    for (int c = tid; c < P_COLS * 8; c += 256) {
        const int n  = c >> 3;
        const int kq = c & 7;                 // 8-half granule along k
        const int off  = (n >= 64) ? 64 : 0;
        const int ncol = n & 63;
        __half2 h[4];
        #pragma unroll
        for (int j = 0; j < 4; j++)
            h[j] = __floats2half2_rn(W[(off + kq * 8 + 2 * j) * 64 + ncol],
                                     W[(off + kq * 8 + 2 * j + 1) * 64 + ncol]);
        *reinterpret_cast<uint4*>(Bt + n * ROW_B + kq * 16)
            = *reinterpret_cast<uint4*>(h);
    }

    // Stage A: rows = nodes m0..m0+127, 64 halfs each (convert f32->f16)
    {
        const float4* nf4 = reinterpret_cast<const float4*>(nf);
        for (int c = tid; c < PM * 8; c += 256) {
            const int r  = c >> 3;
            const int kq = c & 7;
            int node = m0 + r;
            if (node >= n_nodes) node = n_nodes - 1;
            float4 v0 = nf4[node * 16 + kq * 2];
            float4 v1 = nf4[node * 16 + kq * 2 + 1];
            __half2 h[4] = { __floats2half2_rn(v0.x, v0.y),
                             __floats2half2_rn(v0.z, v0.w),
                             __floats2half2_rn(v1.x, v1.y),
                             __floats2half2_rn(v1.z, v1.w) };
            *reinterpret_cast<uint4*>(As + r * ROW_B + kq * 16)
                = *reinterpret_cast<uint4*>(h);
        }
    }
    __syncthreads();

    // Warp tiling: wm = wid&3 -> rows 32*wm..+32; wn = wid>>2 -> cols 64*wn..+64
    const int wm = wid & 3;
    const int wn = wid >> 2;
    const int g  = lid >> 2;
    const int cc = lid & 3;
    const int r16 = lid & 15;
    const int sel = lid >> 4;

    float acc[2][8][4];
    #pragma unroll
    for (int mt = 0; mt < 2; mt++)
        #pragma unroll
        for (int nt = 0; nt < 8; nt++)
            #pragma unroll
            for (int r = 0; r < 4; r++)
                acc[mt][nt][r] = 0.0f;

    uint32_t aOff[2];
    #pragma unroll
    for (int mt = 0; mt < 2; mt++)
        aOff[mt] = (uint32_t)((wm * 32 + mt * 16 + r16) * ROW_B)
                 + (uint32_t)(sel * 16);

    const int bn_lane = ((lid >> 4) & 1) * 8 + (lid & 7);
    const uint32_t bk16 = (uint32_t)(((lid >> 3) & 1) * 16);

    #pragma unroll
    for (int s = 0; s < 4; s++) {                 // K=64, 16 per step
        const uint32_t koff = (uint32_t)s * 32u;
        uint32_t a[2][4];
        #pragma unroll
        for (int mt = 0; mt < 2; mt++)
            ldsm_x4(a[mt][0], a[mt][1], a[mt][2], a[mt][3],
                    a_addr + aOff[mt] + koff);
        #pragma unroll
        for (int p = 0; p < 4; p++) {             // 4 ldsm -> 8 nt frags
            uint32_t r0, r1, r2, r3;
            const uint32_t bF = bt_addr
                + (uint32_t)((wn * 64 + p * 16 + bn_lane) * ROW_B) + bk16;
            ldsm_x4(r0, r1, r2, r3, bF + koff);
            #pragma unroll
            for (int mt = 0; mt < 2; mt++) {
                mma_16x8x16_f16(acc[mt][2 * p + 0], a[mt], r0, r1);
                mma_16x8x16_f16(acc[mt][2 * p + 1], a[mt], r2, r3);
            }
        }
    }

    // Epilogue: +bias on cols<64, store f32 into g_P
    #pragma unroll
    for (int nt = 0; nt < 8; nt++) {
        const int col = wn * 64 + nt * 8 + 2 * cc;
        float2 bj = make_float2(0.f, 0.f);
        if (col < 64) bj = *reinterpret_cast<const float2*>(&bias[col]);
        #pragma unroll
        for (int mt = 0; mt < 2; mt++) {
            const int node0 = m0 + wm * 32 + mt * 16 + g;
            if (node0 < n_nodes) {
                float2 r = make_float2(acc[mt][nt][0] + bj.x,
                                       acc[mt][nt][1] + bj.y);
                *reinterpret_cast<float2*>(&g_P[node0 * P_COLS + col]) = r;
            }
            const int node1 = node0 + 8;
            if (node1 < n_nodes) {
                float2 r = make_float2(acc[mt][nt][2] + bj.x,
                                       acc[mt][nt][3] + bj.y);
                *reinterpret_cast<float2*>(&g_P[node1 * P_COLS + col]) = r;
            }
        }
    }
}

// ---- Edge kernel: out[e] = tanh(P[recv][0:64] + P[send][64:128]) ----
__global__ __launch_bounds__(256)
void edge_kernel(const int* __restrict__ senders,
                 const int* __restrict__ receivers,
                 float* __restrict__ out,
                 int n_edges)
{
    const int t = blockIdx.x * 256 + threadIdx.x;
    const int e = t >> 3;
    const int sub = t & 7;             // 8 cols per thread
    if (e >= n_edges) return;

    const int r = __ldg(&receivers[e]);
    const int s = __ldg(&senders[e]);

    const float4* pr = reinterpret_cast<const float4*>(&g_P[r * P_COLS + sub * 8]);
    const float4* ps = reinterpret_cast<const float4*>(&g_P[s * P_COLS + 64 + sub * 8]);
    float4 a0 = pr[0], a1 = pr[1];
    float4 b0 = ps[0], b1 = ps[1];

    float4 o0, o1;
    o0.x = tanh_fast(a0.x + b0.x);
    o0.y = tanh_fast(a0.y + b0.y);
    o0.z = tanh_fast(a0.z + b0.z);
    o0.w = tanh_fast(a0.w + b0.w);
    o1.x = tanh_fast(a1.x + b1.x);
    o1.y = tanh_fast(a1.y + b1.y);
    o1.z = tanh_fast(a1.z + b1.z);
    o1.w = tanh_fast(a1.w + b1.w);

    float4* op = reinterpret_cast<float4*>(&out[(size_t)e * 64 + sub * 8]);
    op[0] = o0;
    op[1] = o1;
}

extern "C" void kernel_launch(void* const* d_in, const int* in_sizes, int n_in,
                              void* d_out, int out_size)
{
    const float* node_feats = (const float*)d_in[0];
    const int*   senders    = (const int*)d_in[1];
    const int*   receivers  = (const int*)d_in[2];
    const float* W          = (const float*)d_in[3];
    const float* b          = (const float*)d_in[4];
    float*       out        = (float*)d_out;

    const int n_nodes = in_sizes[0] / D_FEAT;
    const int n_edges = in_sizes[1];

    static bool attr_set = false;
    if (!attr_set) {
        cudaFuncSetAttribute(precompute_P_kernel,
                             cudaFuncAttributeMaxDynamicSharedMemorySize, PRE_SMEM);
        attr_set = true;
    }

    const int pre_grid = (n_nodes + PM - 1) / PM;
    precompute_P_kernel<<<pre_grid, 256, PRE_SMEM>>>(node_feats, W, b, n_nodes);

    const int edge_grid = (n_edges * 8 + 255) / 256;
    edge_kernel<<<edge_grid, 256>>>(senders, receivers, out, n_edges);
}

// round 10
// speedup vs baseline: 4.8803x; 1.0510x over previous
#include <cuda_runtime.h>
#include <cuda_fp16.h>
#include <cstdint>

// NoiseNet: out[e,:] = tanh( concat(nf[recv[e]], nf[send[e]]) @ W + b )
// Factored:  P[n][0:64]  = nf[n] @ W[0:64,:]  + b   (recv table, bias folded)
//            P[n][64:128]= nf[n] @ W[64:128,:]      (send table)
//            out[e]      = tanh( P[recv[e]][0:64] + P[send[e]][64:128] )
// P stored fp16 (halves the L2-bound gather traffic of the edge kernel).

#define D_FEAT 64
#define P_COLS 128
#define MAX_NODES 50000

#define PM 128              // nodes per precompute CTA
#define ROW_B 144           // 64 halfs (128B) + 16B pad: conflict-free LDSM
#define PRE_SMEM (2 * PM * ROW_B)

__device__ __half g_P[MAX_NODES * P_COLS];   // 12.8 MB node table (L2-resident)

__device__ __forceinline__ uint32_t smem_u32(const void* p) {
    uint32_t a;
    asm("{ .reg .u64 t; cvta.to.shared.u64 t, %1; cvt.u32.u64 %0, t; }" : "=r"(a) : "l"(p));
    return a;
}
__device__ __forceinline__ float tanh_fast(float x) {
    float y;
    asm("tanh.approx.f32 %0, %1;" : "=f"(y) : "f"(x));
    return y;
}
__device__ __forceinline__ void ldsm_x4(uint32_t& r0, uint32_t& r1,
                                        uint32_t& r2, uint32_t& r3, uint32_t addr) {
    asm volatile("ldmatrix.sync.aligned.m8n8.x4.shared.b16 {%0,%1,%2,%3}, [%4];"
                 : "=r"(r0), "=r"(r1), "=r"(r2), "=r"(r3) : "r"(addr));
}
__device__ __forceinline__ void mma_16x8x16_f16(float c[4], const uint32_t a[4],
                                                uint32_t b0, uint32_t b1) {
    asm volatile(
        "mma.sync.aligned.m16n8k16.row.col.f32.f16.f16.f32 "
        "{%0,%1,%2,%3}, {%4,%5,%6,%7}, {%8,%9}, {%0,%1,%2,%3};"
        : "+f"(c[0]), "+f"(c[1]), "+f"(c[2]), "+f"(c[3])
        : "r"(a[0]), "r"(a[1]), "r"(a[2]), "r"(a[3]), "r"(b0), "r"(b1));
}

// ---- Precompute: P[m0..m0+128][128] = nf @ [Wtop | Wbot] (+bias on cols<64) ----
__global__ __launch_bounds__(256)
void precompute_P_kernel(const float* __restrict__ nf,
                         const float* __restrict__ W,
                         const float* __restrict__ bias,
                         int n_nodes)
{
    extern __shared__ char smem[];
    char* As = smem;                    // [128 rows][ROW_B]  fp16 node feats
    char* Bt = smem + PM * ROW_B;       // [128 n][ROW_B]     fp16 Wcat, n-major

    const int tid = threadIdx.x;
    const int wid = tid >> 5;
    const int lid = tid & 31;
    const int m0  = blockIdx.x * PM;
    const uint32_t a_addr  = smem_u32(As);
    const uint32_t bt_addr = smem_u32(Bt);

    // Stage Bt[n][k]: n<64 -> W[k][n]; n>=64 -> W[64+k][n-64]
    for (int c = tid; c < P_COLS * 8; c += 256) {
        const int n  = c >> 3;
        const int kq = c & 7;
        const int off  = (n >= 64) ? 64 : 0;
        const int ncol = n & 63;
        __half2 h[4];
        #pragma unroll
        for (int j = 0; j < 4; j++)
            h[j] = __floats2half2_rn(W[(off + kq * 8 + 2 * j) * 64 + ncol],
                                     W[(off + kq * 8 + 2 * j + 1) * 64 + ncol]);
        *reinterpret_cast<uint4*>(Bt + n * ROW_B + kq * 16)
            = *reinterpret_cast<uint4*>(h);
    }

    // Stage A: rows = nodes m0..m0+127, 64 halfs each (convert f32->f16)
    {
        const float4* nf4 = reinterpret_cast<const float4*>(nf);
        for (int c = tid; c < PM * 8; c += 256) {
            const int r  = c >> 3;
            const int kq = c & 7;
            int node = m0 + r;
            if (node >= n_nodes) node = n_nodes - 1;
            float4 v0 = nf4[node * 16 + kq * 2];
            float4 v1 = nf4[node * 16 + kq * 2 + 1];
            __half2 h[4] = { __floats2half2_rn(v0.x, v0.y),
                             __floats2half2_rn(v0.z, v0.w),
                             __floats2half2_rn(v1.x, v1.y),
                             __floats2half2_rn(v1.z, v1.w) };
            *reinterpret_cast<uint4*>(As + r * ROW_B + kq * 16)
                = *reinterpret_cast<uint4*>(h);
        }
    }
    __syncthreads();

    // Warp tiling: wm = wid&3 rows 32*wm..+32; wn = wid>>2 cols 64*wn..+64
    const int wm = wid & 3;
    const int wn = wid >> 2;
    const int g  = lid >> 2;
    const int cc = lid & 3;
    const int r16 = lid & 15;
    const int sel = lid >> 4;

    float acc[2][8][4];
    #pragma unroll
    for (int mt = 0; mt < 2; mt++)
        #pragma unroll
        for (int nt = 0; nt < 8; nt++)
            #pragma unroll
            for (int r = 0; r < 4; r++)
                acc[mt][nt][r] = 0.0f;

    uint32_t aOff[2];
    #pragma unroll
    for (int mt = 0; mt < 2; mt++)
        aOff[mt] = (uint32_t)((wm * 32 + mt * 16 + r16) * ROW_B)
                 + (uint32_t)(sel * 16);

    const int bn_lane = ((lid >> 4) & 1) * 8 + (lid & 7);
    const uint32_t bk16 = (uint32_t)(((lid >> 3) & 1) * 16);

    #pragma unroll
    for (int s = 0; s < 4; s++) {                 // K=64, 16 per step
        const uint32_t koff = (uint32_t)s * 32u;
        uint32_t a[2][4];
        #pragma unroll
        for (int mt = 0; mt < 2; mt++)
            ldsm_x4(a[mt][0], a[mt][1], a[mt][2], a[mt][3],
                    a_addr + aOff[mt] + koff);
        #pragma unroll
        for (int p = 0; p < 4; p++) {
            uint32_t r0, r1, r2, r3;
            const uint32_t bF = bt_addr
                + (uint32_t)((wn * 64 + p * 16 + bn_lane) * ROW_B) + bk16;
            ldsm_x4(r0, r1, r2, r3, bF + koff);
            #pragma unroll
            for (int mt = 0; mt < 2; mt++) {
                mma_16x8x16_f16(acc[mt][2 * p + 0], a[mt], r0, r1);
                mma_16x8x16_f16(acc[mt][2 * p + 1], a[mt], r2, r3);
            }
        }
    }

    // Epilogue: +bias on cols<64, store fp16 into g_P (half2 per store)
    #pragma unroll
    for (int nt = 0; nt < 8; nt++) {
        const int col = wn * 64 + nt * 8 + 2 * cc;
        float2 bj = make_float2(0.f, 0.f);
        if (col < 64) bj = *reinterpret_cast<const float2*>(&bias[col]);
        #pragma unroll
        for (int mt = 0; mt < 2; mt++) {
            const int node0 = m0 + wm * 32 + mt * 16 + g;
            if (node0 < n_nodes) {
                __half2 h = __floats2half2_rn(acc[mt][nt][0] + bj.x,
                                              acc[mt][nt][1] + bj.y);
                *reinterpret_cast<__half2*>(&g_P[node0 * P_COLS + col]) = h;
            }
            const int node1 = node0 + 8;
            if (node1 < n_nodes) {
                __half2 h = __floats2half2_rn(acc[mt][nt][2] + bj.x,
                                              acc[mt][nt][3] + bj.y);
                *reinterpret_cast<__half2*>(&g_P[node1 * P_COLS + col]) = h;
            }
        }
    }
}

// ---- Edge kernel: out[e] = tanh(P[recv][0:64] + P[send][64:128]) ----
__global__ __launch_bounds__(256)
void edge_kernel(const int* __restrict__ senders,
                 const int* __restrict__ receivers,
                 float* __restrict__ out,
                 int n_edges)
{
    const int t = blockIdx.x * 256 + threadIdx.x;
    const int e = t >> 3;
    const int sub = t & 7;             // 8 cols per thread
    if (e >= n_edges) return;

    const int r = __ldg(&receivers[e]);
    const int s = __ldg(&senders[e]);

    // 8 halfs (16B) from each table half
    uint4 ar = *reinterpret_cast<const uint4*>(&g_P[r * P_COLS + sub * 8]);
    uint4 as = *reinterpret_cast<const uint4*>(&g_P[s * P_COLS + 64 + sub * 8]);

    const __half2* hr = reinterpret_cast<const __half2*>(&ar);
    const __half2* hs = reinterpret_cast<const __half2*>(&as);

    float4 o0, o1;
    {
        float2 fr = __half22float2(hr[0]);
        float2 fs = __half22float2(hs[0]);
        o0.x = tanh_fast(fr.x + fs.x);
        o0.y = tanh_fast(fr.y + fs.y);
        fr = __half22float2(hr[1]);
        fs = __half22float2(hs[1]);
        o0.z = tanh_fast(fr.x + fs.x);
        o0.w = tanh_fast(fr.y + fs.y);
        fr = __half22float2(hr[2]);
        fs = __half22float2(hs[2]);
        o1.x = tanh_fast(fr.x + fs.x);
        o1.y = tanh_fast(fr.y + fs.y);
        fr = __half22float2(hr[3]);
        fs = __half22float2(hs[3]);
        o1.z = tanh_fast(fr.x + fs.x);
        o1.w = tanh_fast(fr.y + fs.y);
    }

    float4* op = reinterpret_cast<float4*>(&out[(size_t)e * 64 + sub * 8]);
    op[0] = o0;
    op[1] = o1;
}

extern "C" void kernel_launch(void* const* d_in, const int* in_sizes, int n_in,
                              void* d_out, int out_size)
{
    const float* node_feats = (const float*)d_in[0];
    const int*   senders    = (const int*)d_in[1];
    const int*   receivers  = (const int*)d_in[2];
    const float* W          = (const float*)d_in[3];
    const float* b          = (const float*)d_in[4];
    float*       out        = (float*)d_out;

    const int n_nodes = in_sizes[0] / D_FEAT;
    const int n_edges = in_sizes[1];

    static bool attr_set = false;
    if (!attr_set) {
        cudaFuncSetAttribute(precompute_P_kernel,
                             cudaFuncAttributeMaxDynamicSharedMemorySize, PRE_SMEM);
        attr_set = true;
    }

    const int pre_grid = (n_nodes + PM - 1) / PM;
    precompute_P_kernel<<<pre_grid, 256, PRE_SMEM>>>(node_feats, W, b, n_nodes);

    const int edge_grid = (n_edges * 8 + 255) / 256;
    edge_kernel<<<edge_grid, 256>>>(senders, receivers, out, n_edges);
}